// round 1
// baseline (speedup 1.0000x reference)
#include <cuda_runtime.h>
#include <math.h>

// ---------------- Problem dims ----------------
#define B_  2
#define T_  2048
#define D_  1024
#define H_  16
#define HS_ 64
#define BT_ (B_*T_)      // 4096
#define BH_ (B_*H_)      // 32
#define EPS_ 1e-5f

// ---------------- Scratch (static device memory; no allocations) ----------------
__device__ __align__(16) float g_xln[BT_*D_];                 // 16 MB (LN1 out, reused for LN2 out)
__device__ __align__(16) float g_q  [BT_*D_];                 // 16 MB  [B,T,H,HS]
__device__ __align__(16) float g_k  [BT_*D_];                 // 16 MB
__device__ __align__(16) float g_v  [BT_*D_];                 // 16 MB
__device__ __align__(16) float g_res1[BT_*D_];                // 16 MB (embds + attn)
__device__ __align__(16) float g_ffh[(size_t)BT_*4*D_];       // 64 MB (relu(y@W1+b1))
__device__ __align__(16) float g_rowsum[BH_*T_];              // softmax denominators
__device__ __align__(16) float g_scores[(size_t)BH_*T_*T_];   // 512 MB (lower triangle valid)

// ---------------- LayerNorm: one block per row, D=1024, 256 thr x float4 ----------------
__global__ __launch_bounds__(256) void ln_kernel(const float* __restrict__ x,
                                                 const float* __restrict__ gam,
                                                 const float* __restrict__ bet,
                                                 float* __restrict__ y)
{
    const int row = blockIdx.x;
    const int tid = threadIdx.x;
    const float4 v = *(const float4*)(x + (size_t)row*D_ + tid*4);
    float s  = v.x + v.y + v.z + v.w;
    float s2 = v.x*v.x + v.y*v.y + v.z*v.z + v.w*v.w;
    __shared__ float shs[8], shs2[8], stat[2];
    #pragma unroll
    for (int o = 16; o; o >>= 1) {
        s  += __shfl_xor_sync(0xffffffffu, s,  o);
        s2 += __shfl_xor_sync(0xffffffffu, s2, o);
    }
    if ((tid & 31) == 0) { shs[tid >> 5] = s; shs2[tid >> 5] = s2; }
    __syncthreads();
    if (tid == 0) {
        float ts = 0.f, ts2 = 0.f;
        #pragma unroll
        for (int w = 0; w < 8; ++w) { ts += shs[w]; ts2 += shs2[w]; }
        float mean = ts * (1.0f / D_);
        float var  = ts2 * (1.0f / D_) - mean * mean;
        stat[0] = mean; stat[1] = rsqrtf(var + EPS_);
    }
    __syncthreads();
    const float mean = stat[0], rstd = stat[1];
    const float4 g4 = *(const float4*)(gam + tid*4);
    const float4 b4 = *(const float4*)(bet + tid*4);
    float4 o;
    o.x = (v.x - mean) * rstd * g4.x + b4.x;
    o.y = (v.y - mean) * rstd * g4.y + b4.y;
    o.z = (v.z - mean) * rstd * g4.z + b4.z;
    o.w = (v.w - mean) * rstd * g4.w + b4.w;
    *(float4*)(y + (size_t)row*D_ + tid*4) = o;
}

// ---------------- Generic tiled SGEMM 128x128x16, 8x8 micro-tiles ----------------
// MAPB:   B is the [H, D, HS] weight tensor, logically [K, H*HS] col index n -> W[n>>6][k][n&63]
// HASBIAS/RELU/ADDRES: fused epilogue options.
#define GBM 128
#define GBN 128
#define GBK 16

template<bool MAPB, bool HASBIAS, bool RELU, bool ADDRES>
__global__ __launch_bounds__(256) void sgemm_kernel(
    const float* __restrict__ A, const float* __restrict__ Bm,
    const float* __restrict__ bias, const float* __restrict__ res,
    float* __restrict__ C, int M, int N, int K)
{
    __shared__ float As[GBK][GBM];
    __shared__ float Bs[GBK][GBN];
    const int tid = threadIdx.x;
    const int m0 = blockIdx.y * GBM;
    const int n0 = blockIdx.x * GBN;
    const int tx = tid & 15, ty = tid >> 4;

    float acc[8][8];
    #pragma unroll
    for (int i = 0; i < 8; ++i)
        #pragma unroll
        for (int j = 0; j < 8; ++j) acc[i][j] = 0.f;

    for (int k0 = 0; k0 < K; k0 += GBK) {
        #pragma unroll
        for (int it = 0; it < 2; ++it) {
            const int id = tid + it * 256;
            // A tile: 128 rows x 16 k
            const int ra = id >> 2, ca = (id & 3) * 4;
            float4 a = *(const float4*)(A + (size_t)(m0 + ra) * K + k0 + ca);
            As[ca+0][ra] = a.x; As[ca+1][ra] = a.y; As[ca+2][ra] = a.z; As[ca+3][ra] = a.w;
            // B tile: 16 k x 128 n
            const int rb = id >> 5, cb = (id & 31) * 4;
            float4 b;
            if (MAPB) {
                const int col = n0 + cb;
                const int hh = col >> 6, cc = col & 63;   // all 4 elems same head (64%4==0)
                b = *(const float4*)(Bm + ((size_t)hh * K + (k0 + rb)) * HS_ + cc);
            } else {
                b = *(const float4*)(Bm + (size_t)(k0 + rb) * N + n0 + cb);
            }
            *(float4*)(&Bs[rb][cb]) = b;
        }
        __syncthreads();
        #pragma unroll
        for (int kk = 0; kk < GBK; ++kk) {
            float4 a0 = *(const float4*)(&As[kk][ty*8]);
            float4 a1 = *(const float4*)(&As[kk][ty*8+4]);
            float4 b0 = *(const float4*)(&Bs[kk][tx*8]);
            float4 b1 = *(const float4*)(&Bs[kk][tx*8+4]);
            float ra[8] = {a0.x,a0.y,a0.z,a0.w,a1.x,a1.y,a1.z,a1.w};
            float rb[8] = {b0.x,b0.y,b0.z,b0.w,b1.x,b1.y,b1.z,b1.w};
            #pragma unroll
            for (int i = 0; i < 8; ++i)
                #pragma unroll
                for (int j = 0; j < 8; ++j)
                    acc[i][j] += ra[i] * rb[j];
        }
        __syncthreads();
    }

    #pragma unroll
    for (int i = 0; i < 8; ++i) {
        const int m = m0 + ty*8 + i;
        #pragma unroll
        for (int j = 0; j < 8; ++j) {
            const int n = n0 + tx*8 + j;
            float v = acc[i][j];
            if (HASBIAS) v += bias[n];
            if (RELU)    v = fmaxf(v, 0.f);
            if (ADDRES)  v += res[(size_t)m * N + n];
            C[(size_t)m * N + n] = v;
        }
    }
}

// ---------------- Scores: S = scale * Q K^T, lower-triangular tiles only ----------------
__global__ __launch_bounds__(256) void scores_kernel()
{
    const int jt = blockIdx.x, it = blockIdx.y, bh = blockIdx.z;
    if (jt > it) return;
    const int b = bh >> 4, h = bh & 15;
    __shared__ float Qs[HS_][64];   // [e][row]
    __shared__ float Ks[HS_][64];   // [e][col]
    const int tid = threadIdx.x;
    #pragma unroll
    for (int l = 0; l < 4; ++l) {
        const int id = tid + l * 256;      // 64 rows x 16 float4
        const int r  = id >> 4;
        const int e4 = (id & 15) * 4;
        float4 qv = *(const float4*)(g_q + ((((size_t)b*T_ + it*64 + r)*H_ + h) << 6) + e4);
        Qs[e4+0][r] = qv.x; Qs[e4+1][r] = qv.y; Qs[e4+2][r] = qv.z; Qs[e4+3][r] = qv.w;
        float4 kv = *(const float4*)(g_k + ((((size_t)b*T_ + jt*64 + r)*H_ + h) << 6) + e4);
        Ks[e4+0][r] = kv.x; Ks[e4+1][r] = kv.y; Ks[e4+2][r] = kv.z; Ks[e4+3][r] = kv.w;
    }
    __syncthreads();
    const int tx = tid & 15, ty = tid >> 4;
    float acc[4][4];
    #pragma unroll
    for (int i = 0; i < 4; ++i)
        #pragma unroll
        for (int j = 0; j < 4; ++j) acc[i][j] = 0.f;
    #pragma unroll 16
    for (int e = 0; e < HS_; ++e) {
        float ra[4], rb[4];
        #pragma unroll
        for (int i = 0; i < 4; ++i) ra[i] = Qs[e][ty*4+i];
        #pragma unroll
        for (int j = 0; j < 4; ++j) rb[j] = Ks[e][tx*4+j];
        #pragma unroll
        for (int i = 0; i < 4; ++i)
            #pragma unroll
            for (int j = 0; j < 4; ++j) acc[i][j] += ra[i] * rb[j];
    }
    const size_t base = (size_t)bh * T_ * T_;
    #pragma unroll
    for (int i = 0; i < 4; ++i) {
        const int row = it*64 + ty*4 + i;
        #pragma unroll
        for (int j = 0; j < 4; ++j) {
            const int col = jt*64 + tx*4 + j;
            g_scores[base + (size_t)row * T_ + col] = acc[i][j] * 0.03125f;  // D^-0.5 = 1/32
        }
    }
}

// ---------------- Row softmax (unnormalized exp + rowsum), causal: j in [0, i] ----------------
__global__ __launch_bounds__(128) void softmax_kernel()
{
    const int row = blockIdx.x;          // bh*T + i
    const int bh = row >> 11;
    const int i  = row & (T_ - 1);
    float* S = g_scores + (size_t)bh * T_ * T_ + (size_t)i * T_;
    const int len = i + 1;
    const int tid = threadIdx.x;
    __shared__ float red[4], bcast;

    float mx = -1e30f;
    for (int j = tid; j < len; j += 128) mx = fmaxf(mx, S[j]);
    #pragma unroll
    for (int o = 16; o; o >>= 1) mx = fmaxf(mx, __shfl_xor_sync(0xffffffffu, mx, o));
    if ((tid & 31) == 0) red[tid >> 5] = mx;
    __syncthreads();
    if (tid == 0) bcast = fmaxf(fmaxf(red[0], red[1]), fmaxf(red[2], red[3]));
    __syncthreads();
    mx = bcast;

    float sum = 0.f;
    for (int j = tid; j < len; j += 128) {
        float e = __expf(S[j] - mx);
        S[j] = e;
        sum += e;
    }
    #pragma unroll
    for (int o = 16; o; o >>= 1) sum += __shfl_xor_sync(0xffffffffu, sum, o);
    if ((tid & 31) == 0) red[tid >> 5] = sum;
    __syncthreads();
    if (tid == 0) g_rowsum[row] = red[0] + red[1] + red[2] + red[3];
}

// ---------------- PV: O = P V / rowsum, fused head-concat + residual add ----------------
__global__ __launch_bounds__(256) void pv_kernel(const float* __restrict__ embds,
                                                 float* __restrict__ out)
{
    const int it = blockIdx.x, bh = blockIdx.y;
    const int b = bh >> 4, h = bh & 15;
    __shared__ float Ps[64][64];   // [row][key]
    __shared__ float Vs[64][64];   // [key][e]
    const int tid = threadIdx.x, tx = tid & 15, ty = tid >> 4;
    const int i0 = it * 64;
    const size_t sbase = (size_t)bh * T_ * T_;

    float acc[4][4];
    #pragma unroll
    for (int i = 0; i < 4; ++i)
        #pragma unroll
        for (int j = 0; j < 4; ++j) acc[i][j] = 0.f;

    for (int jt = 0; jt <= it; ++jt) {
        const int j0 = jt * 64;
        #pragma unroll
        for (int l = 0; l < 4; ++l) {
            const int id = tid + l * 256;
            const int r  = id >> 4;
            const int c4 = (id & 15) * 4;
            float4 p = *(const float4*)(g_scores + sbase + (size_t)(i0 + r) * T_ + j0 + c4);
            const int ig = i0 + r;   // mask j>i (only fires in diagonal tile; garbage there)
            if (j0 + c4 + 0 > ig) p.x = 0.f;
            if (j0 + c4 + 1 > ig) p.y = 0.f;
            if (j0 + c4 + 2 > ig) p.z = 0.f;
            if (j0 + c4 + 3 > ig) p.w = 0.f;
            *(float4*)(&Ps[r][c4]) = p;
            float4 vv = *(const float4*)(g_v + ((((size_t)b*T_ + j0 + r)*H_ + h) << 6) + c4);
            *(float4*)(&Vs[r][c4]) = vv;
        }
        __syncthreads();
        #pragma unroll 16
        for (int c = 0; c < 64; ++c) {
            float ra[4], rb[4];
            #pragma unroll
            for (int i = 0; i < 4; ++i) ra[i] = Ps[ty*4+i][c];
            #pragma unroll
            for (int j = 0; j < 4; ++j) rb[j] = Vs[c][tx*4+j];
            #pragma unroll
            for (int i = 0; i < 4; ++i)
                #pragma unroll
                for (int j = 0; j < 4; ++j) acc[i][j] += ra[i] * rb[j];
        }
        __syncthreads();
    }

    #pragma unroll
    for (int i = 0; i < 4; ++i) {
        const int t = i0 + ty*4 + i;
        const float inv = 1.0f / g_rowsum[bh * T_ + t];
        #pragma unroll
        for (int j = 0; j < 4; ++j) {
            const int d = h * HS_ + tx*4 + j;
            const size_t o = ((size_t)b * T_ + t) * D_ + d;
            out[o] = embds[o] + acc[i][j] * inv;
        }
    }
}

// ---------------- Launcher ----------------
extern "C" void kernel_launch(void* const* d_in, const int* in_sizes, int n_in,
                              void* d_out, int out_size)
{
    const float* embds = (const float*)d_in[0];
    const float* Wq    = (const float*)d_in[1];
    const float* Wk    = (const float*)d_in[2];
    const float* Wv    = (const float*)d_in[3];
    const float* ln1g  = (const float*)d_in[4];
    const float* ln1b  = (const float*)d_in[5];
    const float* ln2g  = (const float*)d_in[6];
    const float* ln2b  = (const float*)d_in[7];
    const float* W1    = (const float*)d_in[8];
    const float* b1    = (const float*)d_in[9];
    const float* W2    = (const float*)d_in[10];
    const float* b2    = (const float*)d_in[11];
    float* out = (float*)d_out;

    float *xln, *q, *k, *v, *res1, *ffh;
    cudaGetSymbolAddress((void**)&xln,  g_xln);
    cudaGetSymbolAddress((void**)&q,    g_q);
    cudaGetSymbolAddress((void**)&k,    g_k);
    cudaGetSymbolAddress((void**)&v,    g_v);
    cudaGetSymbolAddress((void**)&res1, g_res1);
    cudaGetSymbolAddress((void**)&ffh,  g_ffh);

    // 1. LN1
    ln_kernel<<<BT_, 256>>>(embds, ln1g, ln1b, xln);

    // 2. Q, K, V projections -> [B,T,H,HS]
    {
        dim3 grid(D_ / GBN, BT_ / GBM);   // (8, 32)
        sgemm_kernel<true,  false, false, false><<<grid, 256>>>(xln, Wq, nullptr, nullptr, q, BT_, D_, D_);
        sgemm_kernel<true,  false, false, false><<<grid, 256>>>(xln, Wk, nullptr, nullptr, k, BT_, D_, D_);
        sgemm_kernel<true,  false, false, false><<<grid, 256>>>(xln, Wv, nullptr, nullptr, v, BT_, D_, D_);
    }

    // 3. Scores (lower triangle)
    scores_kernel<<<dim3(T_/64, T_/64, BH_), 256>>>();

    // 4. Row softmax
    softmax_kernel<<<BH_ * T_, 128>>>();

    // 5. PV + head concat + residual -> res1
    pv_kernel<<<dim3(T_/64, BH_), 256>>>(embds, res1);

    // 6. LN2
    ln_kernel<<<BT_, 256>>>(res1, ln2g, ln2b, xln);

    // 7. FFN1: relu(y @ W1 + b1) -> ffh
    sgemm_kernel<false, true, true,  false><<<dim3(4*D_ / GBN, BT_ / GBM), 256>>>(xln, W1, b1, nullptr, ffh, BT_, 4*D_, D_);

    // 8. FFN2: ffh @ W2 + b2 + res1 -> out
    sgemm_kernel<false, true, false, true ><<<dim3(D_ / GBN, BT_ / GBM), 256>>>(ffh, W2, b2, res1, out, BT_, D_, 4*D_);
}

// round 2
// speedup vs baseline: 2.4700x; 2.4700x over previous
#include <cuda_runtime.h>
#include <math.h>
#include <stdint.h>

// ---------------- Problem dims ----------------
#define B_  2
#define T_  2048
#define D_  1024
#define H_  16
#define HS_ 64
#define BT_ (B_*T_)      // 4096
#define BH_ (B_*H_)      // 32
#define EPS_ 1e-5f

// ---------------- Scratch (static device memory; no allocations) ----------------
__device__ __align__(16) float g_xln[BT_*D_];
__device__ __align__(16) float g_q  [BT_*D_];                 // [B,T,H,HS]
__device__ __align__(16) float g_k  [BT_*D_];
__device__ __align__(16) float g_v  [BT_*D_];
__device__ __align__(16) float g_res1[BT_*D_];
__device__ __align__(16) float g_ffh[(size_t)BT_*4*D_];
__device__ __align__(16) float g_rowsum[BH_*T_];
__device__ __align__(16) float g_scores[(size_t)BH_*T_*T_];

// ---------------- TF32 helpers ----------------
__device__ __forceinline__ float f2tf(float f) {
    uint32_t r;
    asm("cvt.rna.tf32.f32 %0, %1;" : "=r"(r) : "f"(f));
    return __uint_as_float(r);
}
__device__ __forceinline__ void mma_tf32(float& c0, float& c1, float& c2, float& c3,
                                         float a0, float a1, float a2, float a3,
                                         float b0, float b1)
{
    uint32_t ua0 = __float_as_uint(a0), ua1 = __float_as_uint(a1);
    uint32_t ua2 = __float_as_uint(a2), ua3 = __float_as_uint(a3);
    uint32_t ub0 = __float_as_uint(b0), ub1 = __float_as_uint(b1);
    asm volatile("mma.sync.aligned.m16n8k8.row.col.f32.tf32.tf32.f32 "
                 "{%0,%1,%2,%3}, {%4,%5,%6,%7}, {%8,%9}, {%0,%1,%2,%3};"
                 : "+f"(c0), "+f"(c1), "+f"(c2), "+f"(c3)
                 : "r"(ua0), "r"(ua1), "r"(ua2), "r"(ua3), "r"(ub0), "r"(ub1));
}

// ---------------- LayerNorm ----------------
__global__ __launch_bounds__(256) void ln_kernel(const float* __restrict__ x,
                                                 const float* __restrict__ gam,
                                                 const float* __restrict__ bet,
                                                 float* __restrict__ y)
{
    const int row = blockIdx.x;
    const int tid = threadIdx.x;
    const float4 v = *(const float4*)(x + (size_t)row*D_ + tid*4);
    float s  = v.x + v.y + v.z + v.w;
    float s2 = v.x*v.x + v.y*v.y + v.z*v.z + v.w*v.w;
    __shared__ float shs[8], shs2[8], stat[2];
    #pragma unroll
    for (int o = 16; o; o >>= 1) {
        s  += __shfl_xor_sync(0xffffffffu, s,  o);
        s2 += __shfl_xor_sync(0xffffffffu, s2, o);
    }
    if ((tid & 31) == 0) { shs[tid >> 5] = s; shs2[tid >> 5] = s2; }
    __syncthreads();
    if (tid == 0) {
        float ts = 0.f, ts2 = 0.f;
        #pragma unroll
        for (int w = 0; w < 8; ++w) { ts += shs[w]; ts2 += shs2[w]; }
        float mean = ts * (1.0f / D_);
        float var  = ts2 * (1.0f / D_) - mean * mean;
        stat[0] = mean; stat[1] = rsqrtf(var + EPS_);
    }
    __syncthreads();
    const float mean = stat[0], rstd = stat[1];
    const float4 g4 = *(const float4*)(gam + tid*4);
    const float4 b4 = *(const float4*)(bet + tid*4);
    float4 o;
    o.x = (v.x - mean) * rstd * g4.x + b4.x;
    o.y = (v.y - mean) * rstd * g4.y + b4.y;
    o.z = (v.z - mean) * rstd * g4.z + b4.z;
    o.w = (v.w - mean) * rstd * g4.w + b4.w;
    *(float4*)(y + (size_t)row*D_ + tid*4) = o;
}

// ---------------- TF32 tensor-core GEMM: 128x128 block, BK=32 ----------------
// As[m][k] stride 36 (frag bank: gid*4+tig, conflict-free)
// Bs[k][n] stride 136 (frag bank: tig*8+gid, conflict-free)
#define AS_STRIDE 36
#define BS_STRIDE 136

template<bool MAPB, bool HASBIAS, bool RELU, bool ADDRES>
__global__ __launch_bounds__(256) void tgemm_kernel(
    const float* __restrict__ A, const float* __restrict__ Bm,
    const float* __restrict__ bias, const float* __restrict__ res,
    float* __restrict__ C, int M, int N, int K)
{
    __shared__ float As[128][AS_STRIDE];
    __shared__ float Bs[32][BS_STRIDE];
    const int tid  = threadIdx.x;
    const int m0 = blockIdx.y * 128, n0 = blockIdx.x * 128;
    const int warp = tid >> 5, lane = tid & 31;
    const int gid = lane >> 2, tig = lane & 3;
    const int wm = (warp >> 2) * 64;   // 0,64
    const int wn = (warp & 3) * 32;    // 0,32,64,96

    float acc[4][4][4];
    #pragma unroll
    for (int t = 0; t < 4; ++t)
        #pragma unroll
        for (int u = 0; u < 4; ++u)
            #pragma unroll
            for (int c = 0; c < 4; ++c) acc[t][u][c] = 0.f;

    for (int k0 = 0; k0 < K; k0 += 32) {
        // --- A tile: 128 rows x 32 k ---
        #pragma unroll
        for (int it = 0; it < 4; ++it) {
            const int r  = it * 32 + (tid >> 3);
            const int c4 = (tid & 7) * 4;
            float4 a = *(const float4*)(A + (size_t)(m0 + r) * K + k0 + c4);
            a.x = f2tf(a.x); a.y = f2tf(a.y); a.z = f2tf(a.z); a.w = f2tf(a.w);
            *(float4*)(&As[r][c4]) = a;
        }
        // --- B tile: 32 k x 128 n ---
        #pragma unroll
        for (int it = 0; it < 4; ++it) {
            const int kk = it * 8 + (tid >> 5);
            const int nn = (tid & 31) * 4;
            float4 b;
            if (MAPB) {
                const int col = n0 + nn;
                const int hh = col >> 6, cc = col & 63;
                b = *(const float4*)(Bm + ((size_t)hh * K + (k0 + kk)) * HS_ + cc);
            } else {
                b = *(const float4*)(Bm + (size_t)(k0 + kk) * N + n0 + nn);
            }
            b.x = f2tf(b.x); b.y = f2tf(b.y); b.z = f2tf(b.z); b.w = f2tf(b.w);
            *(float4*)(&Bs[kk][nn]) = b;
        }
        __syncthreads();

        #pragma unroll
        for (int ks = 0; ks < 4; ++ks) {
            const int kb = ks * 8;
            float bf0[4], bf1[4];
            #pragma unroll
            for (int u = 0; u < 4; ++u) {
                bf0[u] = Bs[kb + tig    ][wn + u*8 + gid];
                bf1[u] = Bs[kb + tig + 4][wn + u*8 + gid];
            }
            #pragma unroll
            for (int t = 0; t < 4; ++t) {
                const int rr = wm + t * 16;
                float a0 = As[rr + gid    ][kb + tig];
                float a1 = As[rr + gid + 8][kb + tig];
                float a2 = As[rr + gid    ][kb + tig + 4];
                float a3 = As[rr + gid + 8][kb + tig + 4];
                #pragma unroll
                for (int u = 0; u < 4; ++u)
                    mma_tf32(acc[t][u][0], acc[t][u][1], acc[t][u][2], acc[t][u][3],
                             a0, a1, a2, a3, bf0[u], bf1[u]);
            }
        }
        __syncthreads();
    }

    // --- epilogue ---
    #pragma unroll
    for (int t = 0; t < 4; ++t) {
        #pragma unroll
        for (int u = 0; u < 4; ++u) {
            const int m = m0 + wm + t*16 + gid;
            const int n = n0 + wn + u*8 + tig*2;
            float v0 = acc[t][u][0], v1 = acc[t][u][1];
            float v2 = acc[t][u][2], v3 = acc[t][u][3];
            if (HASBIAS) { float b0 = bias[n], b1 = bias[n+1]; v0 += b0; v1 += b1; v2 += b0; v3 += b1; }
            if (RELU) { v0 = fmaxf(v0, 0.f); v1 = fmaxf(v1, 0.f); v2 = fmaxf(v2, 0.f); v3 = fmaxf(v3, 0.f); }
            if (ADDRES) {
                const float2 r0 = *(const float2*)(res + (size_t)m * N + n);
                const float2 r1 = *(const float2*)(res + (size_t)(m+8) * N + n);
                v0 += r0.x; v1 += r0.y; v2 += r1.x; v3 += r1.y;
            }
            float2 o0 = make_float2(v0, v1), o1 = make_float2(v2, v3);
            *(float2*)(C + (size_t)m * N + n) = o0;
            *(float2*)(C + (size_t)(m+8) * N + n) = o1;
        }
    }
}

// ---------------- Scores (TF32 MMA): S = (1/32) Q K^T, lower-triangular tiles ----------------
// Qs[r][e] stride 68, Ks[j][e] stride 68
__global__ __launch_bounds__(256) void scores_kernel()
{
    const int jt = blockIdx.x, it = blockIdx.y, bh = blockIdx.z;
    if (jt > it) return;
    const int b = bh >> 4, h = bh & 15;
    __shared__ float Qs[64][68];
    __shared__ float Ks[64][68];
    const int tid = threadIdx.x;
    #pragma unroll
    for (int l = 0; l < 4; ++l) {
        const int r  = l * 16 + (tid >> 4);
        const int e4 = (tid & 15) * 4;
        float4 qv = *(const float4*)(g_q + ((((size_t)b*T_ + it*64 + r)*H_ + h) << 6) + e4);
        qv.x = f2tf(qv.x); qv.y = f2tf(qv.y); qv.z = f2tf(qv.z); qv.w = f2tf(qv.w);
        *(float4*)(&Qs[r][e4]) = qv;
        float4 kv = *(const float4*)(g_k + ((((size_t)b*T_ + jt*64 + r)*H_ + h) << 6) + e4);
        kv.x = f2tf(kv.x); kv.y = f2tf(kv.y); kv.z = f2tf(kv.z); kv.w = f2tf(kv.w);
        *(float4*)(&Ks[r][e4]) = kv;
    }
    __syncthreads();
    const int warp = tid >> 5, lane = tid & 31;
    const int gid = lane >> 2, tig = lane & 3;
    const int wm = (warp >> 1) * 16;   // 0..48
    const int wn = (warp & 1) * 32;    // 0,32

    float acc[4][4];
    #pragma unroll
    for (int u = 0; u < 4; ++u)
        #pragma unroll
        for (int c = 0; c < 4; ++c) acc[u][c] = 0.f;

    #pragma unroll
    for (int ks = 0; ks < 8; ++ks) {
        const int kb = ks * 8;
        float a0 = Qs[wm + gid    ][kb + tig];
        float a1 = Qs[wm + gid + 8][kb + tig];
        float a2 = Qs[wm + gid    ][kb + tig + 4];
        float a3 = Qs[wm + gid + 8][kb + tig + 4];
        #pragma unroll
        for (int u = 0; u < 4; ++u) {
            float b0 = Ks[wn + u*8 + gid][kb + tig];
            float b1 = Ks[wn + u*8 + gid][kb + tig + 4];
            mma_tf32(acc[u][0], acc[u][1], acc[u][2], acc[u][3],
                     a0, a1, a2, a3, b0, b1);
        }
    }

    const size_t base = (size_t)bh * T_ * T_;
    #pragma unroll
    for (int u = 0; u < 4; ++u) {
        const int row = it*64 + wm + gid;
        const int col = jt*64 + wn + u*8 + tig*2;
        *(float2*)(g_scores + base + (size_t)row * T_ + col) =
            make_float2(acc[u][0] * 0.03125f, acc[u][1] * 0.03125f);
        *(float2*)(g_scores + base + (size_t)(row+8) * T_ + col) =
            make_float2(acc[u][2] * 0.03125f, acc[u][3] * 0.03125f);
    }
}

// ---------------- Row softmax (unnormalized exp + rowsum) ----------------
__global__ __launch_bounds__(128) void softmax_kernel()
{
    const int row = blockIdx.x;
    const int bh = row >> 11;
    const int i  = row & (T_ - 1);
    float* S = g_scores + (size_t)bh * T_ * T_ + (size_t)i * T_;
    const int len = i + 1;
    const int tid = threadIdx.x;
    __shared__ float red[4], bcast;

    float mx = -1e30f;
    for (int j = tid; j < len; j += 128) mx = fmaxf(mx, S[j]);
    #pragma unroll
    for (int o = 16; o; o >>= 1) mx = fmaxf(mx, __shfl_xor_sync(0xffffffffu, mx, o));
    if ((tid & 31) == 0) red[tid >> 5] = mx;
    __syncthreads();
    if (tid == 0) bcast = fmaxf(fmaxf(red[0], red[1]), fmaxf(red[2], red[3]));
    __syncthreads();
    mx = bcast;

    float sum = 0.f;
    for (int j = tid; j < len; j += 128) {
        float e = __expf(S[j] - mx);
        S[j] = e;
        sum += e;
    }
    #pragma unroll
    for (int o = 16; o; o >>= 1) sum += __shfl_xor_sync(0xffffffffu, sum, o);
    if ((tid & 31) == 0) red[tid >> 5] = sum;
    __syncthreads();
    if (tid == 0) g_rowsum[row] = red[0] + red[1] + red[2] + red[3];
}

// ---------------- PV (TF32 MMA): O = P V / rowsum + head-concat + residual ----------------
// Ps[i][j] stride 68, Vs[j][e] stride 72
__global__ __launch_bounds__(256) void pv_kernel(const float* __restrict__ embds,
                                                 float* __restrict__ out)
{
    const int it = blockIdx.x, bh = blockIdx.y;
    const int b = bh >> 4, h = bh & 15;
    __shared__ float Ps[64][68];
    __shared__ float Vs[64][72];
    const int tid = threadIdx.x;
    const int warp = tid >> 5, lane = tid & 31;
    const int gid = lane >> 2, tig = lane & 3;
    const int wm = (warp >> 1) * 16;
    const int wn = (warp & 1) * 32;
    const int i0 = it * 64;
    const size_t sbase = (size_t)bh * T_ * T_;

    float acc[4][4];
    #pragma unroll
    for (int u = 0; u < 4; ++u)
        #pragma unroll
        for (int c = 0; c < 4; ++c) acc[u][c] = 0.f;

    for (int jt = 0; jt <= it; ++jt) {
        const int j0 = jt * 64;
        #pragma unroll
        for (int l = 0; l < 4; ++l) {
            const int r  = l * 16 + (tid >> 4);
            const int c4 = (tid & 15) * 4;
            float4 p = *(const float4*)(g_scores + sbase + (size_t)(i0 + r) * T_ + j0 + c4);
            const int ig = i0 + r;
            if (j0 + c4 + 0 > ig) p.x = 0.f;
            if (j0 + c4 + 1 > ig) p.y = 0.f;
            if (j0 + c4 + 2 > ig) p.z = 0.f;
            if (j0 + c4 + 3 > ig) p.w = 0.f;
            p.x = f2tf(p.x); p.y = f2tf(p.y); p.z = f2tf(p.z); p.w = f2tf(p.w);
            *(float4*)(&Ps[r][c4]) = p;
            float4 vv = *(const float4*)(g_v + ((((size_t)b*T_ + j0 + r)*H_ + h) << 6) + c4);
            vv.x = f2tf(vv.x); vv.y = f2tf(vv.y); vv.z = f2tf(vv.z); vv.w = f2tf(vv.w);
            *(float4*)(&Vs[r][c4]) = vv;
        }
        __syncthreads();
        #pragma unroll
        for (int ks = 0; ks < 8; ++ks) {
            const int kb = ks * 8;
            float a0 = Ps[wm + gid    ][kb + tig];
            float a1 = Ps[wm + gid + 8][kb + tig];
            float a2 = Ps[wm + gid    ][kb + tig + 4];
            float a3 = Ps[wm + gid + 8][kb + tig + 4];
            #pragma unroll
            for (int u = 0; u < 4; ++u) {
                float b0 = Vs[kb + tig    ][wn + u*8 + gid];
                float b1 = Vs[kb + tig + 4][wn + u*8 + gid];
                mma_tf32(acc[u][0], acc[u][1], acc[u][2], acc[u][3],
                         a0, a1, a2, a3, b0, b1);
            }
        }
        __syncthreads();
    }

    const int t0 = i0 + wm + gid;
    const float inv0 = 1.0f / g_rowsum[bh * T_ + t0];
    const float inv1 = 1.0f / g_rowsum[bh * T_ + t0 + 8];
    #pragma unroll
    for (int u = 0; u < 4; ++u) {
        const int d = h * HS_ + wn + u*8 + tig*2;
        const size_t o0 = ((size_t)b * T_ + t0) * D_ + d;
        const size_t o1 = ((size_t)b * T_ + t0 + 8) * D_ + d;
        const float2 e0 = *(const float2*)(embds + o0);
        const float2 e1 = *(const float2*)(embds + o1);
        *(float2*)(out + o0) = make_float2(e0.x + acc[u][0]*inv0, e0.y + acc[u][1]*inv0);
        *(float2*)(out + o1) = make_float2(e1.x + acc[u][2]*inv1, e1.y + acc[u][3]*inv1);
    }
}

// ---------------- Launcher ----------------
extern "C" void kernel_launch(void* const* d_in, const int* in_sizes, int n_in,
                              void* d_out, int out_size)
{
    const float* embds = (const float*)d_in[0];
    const float* Wq    = (const float*)d_in[1];
    const float* Wk    = (const float*)d_in[2];
    const float* Wv    = (const float*)d_in[3];
    const float* ln1g  = (const float*)d_in[4];
    const float* ln1b  = (const float*)d_in[5];
    const float* ln2g  = (const float*)d_in[6];
    const float* ln2b  = (const float*)d_in[7];
    const float* W1    = (const float*)d_in[8];
    const float* b1    = (const float*)d_in[9];
    const float* W2    = (const float*)d_in[10];
    const float* b2    = (const float*)d_in[11];
    float* out = (float*)d_out;

    float *xln, *q, *k, *v, *res1, *ffh;
    cudaGetSymbolAddress((void**)&xln,  g_xln);
    cudaGetSymbolAddress((void**)&q,    g_q);
    cudaGetSymbolAddress((void**)&k,    g_k);
    cudaGetSymbolAddress((void**)&v,    g_v);
    cudaGetSymbolAddress((void**)&res1, g_res1);
    cudaGetSymbolAddress((void**)&ffh,  g_ffh);

    // 1. LN1
    ln_kernel<<<BT_, 256>>>(embds, ln1g, ln1b, xln);

    // 2. Q, K, V projections -> [B,T,H,HS]
    {
        dim3 grid(D_ / 128, BT_ / 128);   // (8, 32)
        tgemm_kernel<true,  false, false, false><<<grid, 256>>>(xln, Wq, nullptr, nullptr, q, BT_, D_, D_);
        tgemm_kernel<true,  false, false, false><<<grid, 256>>>(xln, Wk, nullptr, nullptr, k, BT_, D_, D_);
        tgemm_kernel<true,  false, false, false><<<grid, 256>>>(xln, Wv, nullptr, nullptr, v, BT_, D_, D_);
    }

    // 3. Scores (lower triangle, TF32 MMA)
    scores_kernel<<<dim3(T_/64, T_/64, BH_), 256>>>();

    // 4. Row softmax
    softmax_kernel<<<BH_ * T_, 128>>>();

    // 5. PV + head concat + residual -> res1
    pv_kernel<<<dim3(T_/64, BH_), 256>>>(embds, res1);

    // 6. LN2
    ln_kernel<<<BT_, 256>>>(res1, ln2g, ln2b, xln);

    // 7. FFN1: relu(y @ W1 + b1) -> ffh
    tgemm_kernel<false, true, true,  false><<<dim3(4*D_ / 128, BT_ / 128), 256>>>(xln, W1, b1, nullptr, ffh, BT_, 4*D_, D_);

    // 8. FFN2: ffh @ W2 + b2 + res1 -> out
    tgemm_kernel<false, true, false, true ><<<dim3(D_ / 128, BT_ / 128), 256>>>(ffh, W2, b2, res1, out, BT_, D_, 4*D_);
}

// round 7
// speedup vs baseline: 2.8162x; 1.1402x over previous
#include <cuda_runtime.h>
#include <math.h>
#include <stdint.h>

// ---------------- Problem dims ----------------
#define B_  2
#define T_  2048
#define D_  1024
#define H_  16
#define HS_ 64
#define BT_ (B_*T_)      // 4096
#define BH_ (B_*H_)      // 32
#define EPS_ 1e-5f

// ---------------- Scratch (static device memory; no allocations) ----------------
__device__ __align__(16) float g_xln [BT_*D_];
__device__ __align__(16) float g_q   [BT_*D_];     // [B,T,H,HS]
__device__ __align__(16) float g_k   [BT_*D_];
__device__ __align__(16) float g_v   [BT_*D_];
__device__ __align__(16) float g_res1[BT_*D_];
__device__ __align__(16) float g_ffh [(size_t)BT_*4*D_];

// ---------------- TF32 helpers (R2 exact) ----------------
__device__ __forceinline__ float f2tf(float f) {
    uint32_t r;
    asm("cvt.rna.tf32.f32 %0, %1;" : "=r"(r) : "f"(f));
    return __uint_as_float(r);
}
__device__ __forceinline__ void mma_tf32(float& c0, float& c1, float& c2, float& c3,
                                         float a0, float a1, float a2, float a3,
                                         float b0, float b1)
{
    uint32_t ua0 = __float_as_uint(a0), ua1 = __float_as_uint(a1);
    uint32_t ua2 = __float_as_uint(a2), ua3 = __float_as_uint(a3);
    uint32_t ub0 = __float_as_uint(b0), ub1 = __float_as_uint(b1);
    asm volatile("mma.sync.aligned.m16n8k8.row.col.f32.tf32.tf32.f32 "
                 "{%0,%1,%2,%3}, {%4,%5,%6,%7}, {%8,%9}, {%0,%1,%2,%3};"
                 : "+f"(c0), "+f"(c1), "+f"(c2), "+f"(c3)
                 : "r"(ua0), "r"(ua1), "r"(ua2), "r"(ua3), "r"(ub0), "r"(ub1));
}

// ---------------- LayerNorm (R2 exact) ----------------
__global__ __launch_bounds__(256) void ln_kernel(const float* __restrict__ x,
                                                 const float* __restrict__ gam,
                                                 const float* __restrict__ bet,
                                                 float* __restrict__ y)
{
    const int row = blockIdx.x;
    const int tid = threadIdx.x;
    const float4 v = *(const float4*)(x + (size_t)row*D_ + tid*4);
    float s  = v.x + v.y + v.z + v.w;
    float s2 = v.x*v.x + v.y*v.y + v.z*v.z + v.w*v.w;
    __shared__ float shs[8], shs2[8], stat[2];
    #pragma unroll
    for (int o = 16; o; o >>= 1) {
        s  += __shfl_xor_sync(0xffffffffu, s,  o);
        s2 += __shfl_xor_sync(0xffffffffu, s2, o);
    }
    if ((tid & 31) == 0) { shs[tid >> 5] = s; shs2[tid >> 5] = s2; }
    __syncthreads();
    if (tid == 0) {
        float ts = 0.f, ts2 = 0.f;
        #pragma unroll
        for (int w = 0; w < 8; ++w) { ts += shs[w]; ts2 += shs2[w]; }
        float mean = ts * (1.0f / D_);
        float var  = ts2 * (1.0f / D_) - mean * mean;
        stat[0] = mean; stat[1] = rsqrtf(var + EPS_);
    }
    __syncthreads();
    const float mean = stat[0], rstd = stat[1];
    const float4 g4 = *(const float4*)(gam + tid*4);
    const float4 b4 = *(const float4*)(bet + tid*4);
    float4 o;
    o.x = (v.x - mean) * rstd * g4.x + b4.x;
    o.y = (v.y - mean) * rstd * g4.y + b4.y;
    o.z = (v.z - mean) * rstd * g4.z + b4.z;
    o.w = (v.w - mean) * rstd * g4.w + b4.w;
    *(float4*)(y + (size_t)row*D_ + tid*4) = o;
}

// ---------------- TF32 tensor-core GEMM (R2 exact): 128x128 block, BK=32 ----------------
#define AS_STRIDE 36
#define BS_STRIDE 136

template<bool MAPB, bool HASBIAS, bool RELU, bool ADDRES>
__global__ __launch_bounds__(256) void tgemm_kernel(
    const float* __restrict__ A, const float* __restrict__ Bm,
    const float* __restrict__ bias, const float* __restrict__ res,
    float* __restrict__ C, int M, int N, int K)
{
    __shared__ float As[128][AS_STRIDE];
    __shared__ float Bs[32][BS_STRIDE];
    const int tid  = threadIdx.x;
    const int m0 = blockIdx.y * 128, n0 = blockIdx.x * 128;
    const int warp = tid >> 5, lane = tid & 31;
    const int gid = lane >> 2, tig = lane & 3;
    const int wm = (warp >> 2) * 64;   // 0,64
    const int wn = (warp & 3) * 32;    // 0,32,64,96

    float acc[4][4][4];
    #pragma unroll
    for (int t = 0; t < 4; ++t)
        #pragma unroll
        for (int u = 0; u < 4; ++u)
            #pragma unroll
            for (int c = 0; c < 4; ++c) acc[t][u][c] = 0.f;

    for (int k0 = 0; k0 < K; k0 += 32) {
        #pragma unroll
        for (int it = 0; it < 4; ++it) {
            const int r  = it * 32 + (tid >> 3);
            const int c4 = (tid & 7) * 4;
            float4 a = *(const float4*)(A + (size_t)(m0 + r) * K + k0 + c4);
            a.x = f2tf(a.x); a.y = f2tf(a.y); a.z = f2tf(a.z); a.w = f2tf(a.w);
            *(float4*)(&As[r][c4]) = a;
        }
        #pragma unroll
        for (int it = 0; it < 4; ++it) {
            const int kk = it * 8 + (tid >> 5);
            const int nn = (tid & 31) * 4;
            float4 b;
            if (MAPB) {
                const int col = n0 + nn;
                const int hh = col >> 6, cc = col & 63;
                b = *(const float4*)(Bm + ((size_t)hh * K + (k0 + kk)) * HS_ + cc);
            } else {
                b = *(const float4*)(Bm + (size_t)(k0 + kk) * N + n0 + nn);
            }
            b.x = f2tf(b.x); b.y = f2tf(b.y); b.z = f2tf(b.z); b.w = f2tf(b.w);
            *(float4*)(&Bs[kk][nn]) = b;
        }
        __syncthreads();

        #pragma unroll
        for (int ks = 0; ks < 4; ++ks) {
            const int kb = ks * 8;
            float bf0[4], bf1[4];
            #pragma unroll
            for (int u = 0; u < 4; ++u) {
                bf0[u] = Bs[kb + tig    ][wn + u*8 + gid];
                bf1[u] = Bs[kb + tig + 4][wn + u*8 + gid];
            }
            #pragma unroll
            for (int t = 0; t < 4; ++t) {
                const int rr = wm + t * 16;
                float a0 = As[rr + gid    ][kb + tig];
                float a1 = As[rr + gid + 8][kb + tig];
                float a2 = As[rr + gid    ][kb + tig + 4];
                float a3 = As[rr + gid + 8][kb + tig + 4];
                #pragma unroll
                for (int u = 0; u < 4; ++u)
                    mma_tf32(acc[t][u][0], acc[t][u][1], acc[t][u][2], acc[t][u][3],
                             a0, a1, a2, a3, bf0[u], bf1[u]);
            }
        }
        __syncthreads();
    }

    #pragma unroll
    for (int t = 0; t < 4; ++t) {
        #pragma unroll
        for (int u = 0; u < 4; ++u) {
            const int m = m0 + wm + t*16 + gid;
            const int n = n0 + wn + u*8 + tig*2;
            float v0 = acc[t][u][0], v1 = acc[t][u][1];
            float v2 = acc[t][u][2], v3 = acc[t][u][3];
            if (HASBIAS) { float b0 = bias[n], b1 = bias[n+1]; v0 += b0; v1 += b1; v2 += b0; v3 += b1; }
            if (RELU) { v0 = fmaxf(v0, 0.f); v1 = fmaxf(v1, 0.f); v2 = fmaxf(v2, 0.f); v3 = fmaxf(v3, 0.f); }
            if (ADDRES) {
                const float2 r0 = *(const float2*)(res + (size_t)m * N + n);
                const float2 r1 = *(const float2*)(res + (size_t)(m+8) * N + n);
                v0 += r0.x; v1 += r0.y; v2 += r1.x; v3 += r1.y;
            }
            *(float2*)(C + (size_t)m * N + n)       = make_float2(v0, v1);
            *(float2*)(C + (size_t)(m+8) * N + n)   = make_float2(v2, v3);
        }
    }
}

// ---------------- Flash attention: static smem (<48KB), 128 thr, 64-row CTA ----------------
// Each warp owns 16 rows. Keys streamed in 32-chunks. out = embds + softmax(S)V (head-concat).
__global__ __launch_bounds__(128) void flash_kernel(const float* __restrict__ embds,
                                                    float* __restrict__ out)
{
    __shared__ float Qs[64][68];
    __shared__ float Ks[32][68];
    __shared__ float Vs[32][72];
    __shared__ float Ps[64][36];

    const int it = gridDim.x - 1 - blockIdx.x;   // heavy tiles first
    const int bh = blockIdx.y;
    const int b = bh >> 4, h = bh & 15;
    const int tid = threadIdx.x, warp = tid >> 5, lane = tid & 31;
    const int gid = lane >> 2, tig = lane & 3;
    const int i0 = it * 64;
    const int wr = i0 + warp * 16;

    // stage Q tile (round to tf32 on load; matches R2 numerics)
    #pragma unroll
    for (int l = 0; l < 8; ++l) {
        int idx = l * 128 + tid;
        int r = idx >> 4, e4 = (idx & 15) * 4;
        float4 qv = *(const float4*)(g_q + (((size_t)(b*T_ + i0 + r))*H_ + h)*HS_ + e4);
        qv.x = f2tf(qv.x); qv.y = f2tf(qv.y); qv.z = f2tf(qv.z); qv.w = f2tf(qv.w);
        *(float4*)(&Qs[r][e4]) = qv;
    }

    float oacc[8][4];
    #pragma unroll
    for (int u = 0; u < 8; ++u)
        #pragma unroll
        for (int c = 0; c < 4; ++c) oacc[u][c] = 0.f;
    float mrow[2] = {-1e30f, -1e30f};
    float lrow[2] = {0.f, 0.f};

    const int njc = 2*it + 2;
    for (int jc = 0; jc < njc; ++jc) {
        const int j0 = jc * 32;
        __syncthreads();   // previous K/V consumed (also guards initial Qs fill)
        #pragma unroll
        for (int l = 0; l < 4; ++l) {
            int idx = l * 128 + tid;
            int r = idx >> 4, e4 = (idx & 15) * 4;
            const size_t grow = (((size_t)(b*T_ + j0 + r))*H_ + h)*HS_ + e4;
            float4 kv = *(const float4*)(g_k + grow);
            kv.x = f2tf(kv.x); kv.y = f2tf(kv.y); kv.z = f2tf(kv.z); kv.w = f2tf(kv.w);
            *(float4*)(&Ks[r][e4]) = kv;
            float4 vv = *(const float4*)(g_v + grow);
            vv.x = f2tf(vv.x); vv.y = f2tf(vv.y); vv.z = f2tf(vv.z); vv.w = f2tf(vv.w);
            *(float4*)(&Vs[r][e4]) = vv;
        }
        __syncthreads();

        if (j0 <= wr + 15) {     // warp-uniform skip of fully-masked chunks
            // --- S = Q K^T (16 rows x 32 keys) ---
            float sacc[4][4];
            #pragma unroll
            for (int u = 0; u < 4; ++u)
                #pragma unroll
                for (int c = 0; c < 4; ++c) sacc[u][c] = 0.f;
            #pragma unroll
            for (int kc = 0; kc < 8; ++kc) {
                const int kb = kc * 8;
                float a0 = Qs[warp*16 + gid    ][kb + tig];
                float a1 = Qs[warp*16 + gid + 8][kb + tig];
                float a2 = Qs[warp*16 + gid    ][kb + tig + 4];
                float a3 = Qs[warp*16 + gid + 8][kb + tig + 4];
                #pragma unroll
                for (int u = 0; u < 4; ++u) {
                    float b0 = Ks[u*8 + gid][kb + tig];
                    float b1 = Ks[u*8 + gid][kb + tig + 4];
                    mma_tf32(sacc[u][0], sacc[u][1], sacc[u][2], sacc[u][3],
                             a0, a1, a2, a3, b0, b1);
                }
            }

            // --- online softmax on 32-col chunk, P -> smem ---
            const bool maskneed = (j0 + 31 > wr);
            #pragma unroll
            for (int rh = 0; rh < 2; ++rh) {
                const int row = wr + gid + rh*8;
                float tmax = -1e30f;
                #pragma unroll
                for (int u = 0; u < 4; ++u) {
                    float x0 = sacc[u][rh*2    ] * 0.03125f;
                    float x1 = sacc[u][rh*2 + 1] * 0.03125f;
                    if (maskneed) {
                        const int c = j0 + u*8 + tig*2;
                        if (c     > row) x0 = -1e30f;
                        if (c + 1 > row) x1 = -1e30f;
                    }
                    sacc[u][rh*2    ] = x0;
                    sacc[u][rh*2 + 1] = x1;
                    tmax = fmaxf(tmax, fmaxf(x0, x1));
                }
                tmax = fmaxf(tmax, __shfl_xor_sync(0xffffffffu, tmax, 1));
                tmax = fmaxf(tmax, __shfl_xor_sync(0xffffffffu, tmax, 2));
                const float mnew = fmaxf(mrow[rh], tmax);
                const float corr = __expf(mrow[rh] - mnew);
                float rsum = 0.f;
                #pragma unroll
                for (int u = 0; u < 4; ++u) {
                    float p0 = __expf(sacc[u][rh*2    ] - mnew);
                    float p1 = __expf(sacc[u][rh*2 + 1] - mnew);
                    rsum += p0 + p1;
                    *(float2*)(&Ps[warp*16 + gid + rh*8][u*8 + tig*2]) =
                        make_float2(f2tf(p0), f2tf(p1));
                }
                #pragma unroll
                for (int uu = 0; uu < 8; ++uu) {
                    oacc[uu][rh*2    ] *= corr;
                    oacc[uu][rh*2 + 1] *= corr;
                }
                rsum += __shfl_xor_sync(0xffffffffu, rsum, 1);
                rsum += __shfl_xor_sync(0xffffffffu, rsum, 2);
                lrow[rh] = lrow[rh] * corr + rsum;
                mrow[rh] = mnew;
            }
            __syncwarp();

            // --- O += P(16x32) V(32x64), warp-local P ---
            #pragma unroll
            for (int kc = 0; kc < 4; ++kc) {
                const int kb = kc * 8;
                float a0 = Ps[warp*16 + gid    ][kb + tig];
                float a1 = Ps[warp*16 + gid + 8][kb + tig];
                float a2 = Ps[warp*16 + gid    ][kb + tig + 4];
                float a3 = Ps[warp*16 + gid + 8][kb + tig + 4];
                #pragma unroll
                for (int u = 0; u < 8; ++u) {
                    float b0 = Vs[kb + tig    ][u*8 + gid];
                    float b1 = Vs[kb + tig + 4][u*8 + gid];
                    mma_tf32(oacc[u][0], oacc[u][1], oacc[u][2], oacc[u][3],
                             a0, a1, a2, a3, b0, b1);
                }
            }
        }
    }

    // --- epilogue: /rowsum + residual, head-concat layout ---
    #pragma unroll
    for (int rh = 0; rh < 2; ++rh) {
        const int t = wr + gid + rh*8;
        const float inv = 1.0f / lrow[rh];
        #pragma unroll
        for (int u = 0; u < 8; ++u) {
            const int d = h * HS_ + u*8 + tig*2;
            const size_t o = ((size_t)(b*T_ + t))*D_ + d;
            const float2 e = *(const float2*)(embds + o);
            *(float2*)(out + o) = make_float2(e.x + oacc[u][rh*2    ]*inv,
                                              e.y + oacc[u][rh*2 + 1]*inv);
        }
    }
}

// ---------------- Launcher (R2 structure; flash replaces scores/softmax/pv) ----------------
extern "C" void kernel_launch(void* const* d_in, const int* in_sizes, int n_in,
                              void* d_out, int out_size)
{
    const float* embds = (const float*)d_in[0];
    const float* Wq    = (const float*)d_in[1];
    const float* Wk    = (const float*)d_in[2];
    const float* Wv    = (const float*)d_in[3];
    const float* ln1g  = (const float*)d_in[4];
    const float* ln1b  = (const float*)d_in[5];
    const float* ln2g  = (const float*)d_in[6];
    const float* ln2b  = (const float*)d_in[7];
    const float* W1    = (const float*)d_in[8];
    const float* b1    = (const float*)d_in[9];
    const float* W2    = (const float*)d_in[10];
    const float* b2    = (const float*)d_in[11];
    float* out = (float*)d_out;

    float *xln, *q, *k, *v, *res1, *ffh;
    cudaGetSymbolAddress((void**)&xln,  g_xln);
    cudaGetSymbolAddress((void**)&q,    g_q);
    cudaGetSymbolAddress((void**)&k,    g_k);
    cudaGetSymbolAddress((void**)&v,    g_v);
    cudaGetSymbolAddress((void**)&res1, g_res1);
    cudaGetSymbolAddress((void**)&ffh,  g_ffh);

    // 1. LN1
    ln_kernel<<<BT_, 256>>>(embds, ln1g, ln1b, xln);

    // 2. Q, K, V projections -> [B,T,H,HS]  (R2 exact: 3 launches, MAPB weight map)
    {
        dim3 grid(D_ / 128, BT_ / 128);   // (8, 32)
        tgemm_kernel<true,  false, false, false><<<grid, 256>>>(xln, Wq, nullptr, nullptr, q, BT_, D_, D_);
        tgemm_kernel<true,  false, false, false><<<grid, 256>>>(xln, Wk, nullptr, nullptr, k, BT_, D_, D_);
        tgemm_kernel<true,  false, false, false><<<grid, 256>>>(xln, Wv, nullptr, nullptr, v, BT_, D_, D_);
    }

    // 3. Flash attention + head-concat + residual -> res1
    flash_kernel<<<dim3(T_/64, BH_), 128>>>(embds, res1);

    // 4. LN2
    ln_kernel<<<BT_, 256>>>(res1, ln2g, ln2b, xln);

    // 5. FFN1: relu(y @ W1 + b1) -> ffh
    tgemm_kernel<false, true, true,  false><<<dim3(4*D_ / 128, BT_ / 128), 256>>>(xln, W1, b1, nullptr, ffh, BT_, 4*D_, D_);

    // 6. FFN2: ffh @ W2 + b2 + res1 -> out
    tgemm_kernel<false, true, false, true ><<<dim3(D_ / 128, BT_ / 128), 256>>>(ffh, W2, b2, res1, out, BT_, D_, 4*D_);
}

// round 8
// speedup vs baseline: 3.2483x; 1.1534x over previous
#include <cuda_runtime.h>
#include <math.h>
#include <stdint.h>

// ---------------- Problem dims ----------------
#define B_  2
#define T_  2048
#define D_  1024
#define H_  16
#define HS_ 64
#define BT_ (B_*T_)      // 4096
#define BH_ (B_*H_)      // 32
#define EPS_ 1e-5f

// ---------------- Scratch (static device memory; no allocations) ----------------
__device__ __align__(16) float g_xln [BT_*D_];
__device__ __align__(16) float g_q   [BT_*D_];     // [B,T,H,HS], tf32-rounded
__device__ __align__(16) float g_k   [BT_*D_];
__device__ __align__(16) float g_v   [BT_*D_];
__device__ __align__(16) float g_res1[BT_*D_];
__device__ __align__(16) float g_ffh [(size_t)BT_*4*D_];

// ---------------- TF32 helpers ----------------
__device__ __forceinline__ float f2tf(float f) {
    uint32_t r;
    asm("cvt.rna.tf32.f32 %0, %1;" : "=r"(r) : "f"(f));
    return __uint_as_float(r);
}
__device__ __forceinline__ void mma_tf32(float& c0, float& c1, float& c2, float& c3,
                                         float a0, float a1, float a2, float a3,
                                         float b0, float b1)
{
    uint32_t ua0 = __float_as_uint(a0), ua1 = __float_as_uint(a1);
    uint32_t ua2 = __float_as_uint(a2), ua3 = __float_as_uint(a3);
    uint32_t ub0 = __float_as_uint(b0), ub1 = __float_as_uint(b1);
    asm volatile("mma.sync.aligned.m16n8k8.row.col.f32.tf32.tf32.f32 "
                 "{%0,%1,%2,%3}, {%4,%5,%6,%7}, {%8,%9}, {%0,%1,%2,%3};"
                 : "+f"(c0), "+f"(c1), "+f"(c2), "+f"(c3)
                 : "r"(ua0), "r"(ua1), "r"(ua2), "r"(ua3), "r"(ub0), "r"(ub1));
}
__device__ __forceinline__ void cp16(float* s, const float* g) {
    uint32_t sa = (uint32_t)__cvta_generic_to_shared(s);
    asm volatile("cp.async.cg.shared.global [%0], [%1], 16;" :: "r"(sa), "l"(g));
}
__device__ __forceinline__ void cp_commit() { asm volatile("cp.async.commit_group;" ::: "memory"); }
template<int N>
__device__ __forceinline__ void cp_wait() { asm volatile("cp.async.wait_group %0;" :: "n"(N) : "memory"); }

// ---------------- LayerNorm (tf32-rounded output: feeds GEMMs only) ----------------
__global__ __launch_bounds__(256) void ln_kernel(const float* __restrict__ x,
                                                 const float* __restrict__ gam,
                                                 const float* __restrict__ bet,
                                                 float* __restrict__ y)
{
    const int row = blockIdx.x;
    const int tid = threadIdx.x;
    const float4 v = *(const float4*)(x + (size_t)row*D_ + tid*4);
    float s  = v.x + v.y + v.z + v.w;
    float s2 = v.x*v.x + v.y*v.y + v.z*v.z + v.w*v.w;
    __shared__ float shs[8], shs2[8], stat[2];
    #pragma unroll
    for (int o = 16; o; o >>= 1) {
        s  += __shfl_xor_sync(0xffffffffu, s,  o);
        s2 += __shfl_xor_sync(0xffffffffu, s2, o);
    }
    if ((tid & 31) == 0) { shs[tid >> 5] = s; shs2[tid >> 5] = s2; }
    __syncthreads();
    if (tid == 0) {
        float ts = 0.f, ts2 = 0.f;
        #pragma unroll
        for (int w = 0; w < 8; ++w) { ts += shs[w]; ts2 += shs2[w]; }
        float mean = ts * (1.0f / D_);
        float var  = ts2 * (1.0f / D_) - mean * mean;
        stat[0] = mean; stat[1] = rsqrtf(var + EPS_);
    }
    __syncthreads();
    const float mean = stat[0], rstd = stat[1];
    const float4 g4 = *(const float4*)(gam + tid*4);
    const float4 b4 = *(const float4*)(bet + tid*4);
    float4 o;
    o.x = f2tf((v.x - mean) * rstd * g4.x + b4.x);
    o.y = f2tf((v.y - mean) * rstd * g4.y + b4.y);
    o.z = f2tf((v.z - mean) * rstd * g4.z + b4.z);
    o.w = f2tf((v.w - mean) * rstd * g4.w + b4.w);
    *(float4*)(y + (size_t)row*D_ + tid*4) = o;
}

// ---------------- cp.async double-buffered TF32 GEMM: 128x128, BK=16, static smem ----------------
// A (activations) pre-rounded by producers; B (weights) rounded at fragment read.
#define AS_STRIDE 20
#define BS_STRIDE 136

template<bool MAPB, bool HASBIAS, bool RELU, bool ADDRES, bool ROUND>
__global__ __launch_bounds__(256) void tgemm_kernel(
    const float* __restrict__ A, const float* __restrict__ Bm,
    const float* __restrict__ bias, const float* __restrict__ res,
    float* __restrict__ C, int M, int N, int K)
{
    __shared__ __align__(16) float As[2][128][AS_STRIDE];
    __shared__ __align__(16) float Bs[2][16][BS_STRIDE];
    const int tid  = threadIdx.x;
    const int m0 = blockIdx.y * 128, n0 = blockIdx.x * 128;
    const int warp = tid >> 5, lane = tid & 31;
    const int gid = lane >> 2, tig = lane & 3;
    const int wm = (warp >> 2) * 64;   // 0,64
    const int wn = (warp & 3) * 32;    // 0,32,64,96

    // per-thread load coords (2 float4 each for A and B per 16-k tile)
    const int lar0 = (tid      ) >> 2, lac0 = ((tid      ) & 3) * 4;
    const int lar1 = (tid + 256) >> 2, lac1 = ((tid + 256) & 3) * 4;
    const int lbk0 = (tid      ) >> 5, lbn0 = ((tid      ) & 31) * 4;
    const int lbk1 = (tid + 256) >> 5, lbn1 = ((tid + 256) & 31) * 4;

    float acc[4][4][4];
    #pragma unroll
    for (int t = 0; t < 4; ++t)
        #pragma unroll
        for (int u = 0; u < 4; ++u)
            #pragma unroll
            for (int c = 0; c < 4; ++c) acc[t][u][c] = 0.f;

    const int ntiles = K >> 4;

    // prologue: stage tile 0 into buffer 0
    {
        cp16(&As[0][lar0][lac0], A + (size_t)(m0 + lar0) * K + lac0);
        cp16(&As[0][lar1][lac1], A + (size_t)(m0 + lar1) * K + lac1);
        if (MAPB) {
            int col0 = n0 + lbn0, col1 = n0 + lbn1;
            cp16(&Bs[0][lbk0][lbn0], Bm + ((size_t)(col0 >> 6) * K + lbk0) * HS_ + (col0 & 63));
            cp16(&Bs[0][lbk1][lbn1], Bm + ((size_t)(col1 >> 6) * K + lbk1) * HS_ + (col1 & 63));
        } else {
            cp16(&Bs[0][lbk0][lbn0], Bm + (size_t)lbk0 * N + n0 + lbn0);
            cp16(&Bs[0][lbk1][lbn1], Bm + (size_t)lbk1 * N + n0 + lbn1);
        }
        cp_commit();
    }

    for (int t = 0; t < ntiles; ++t) {
        const int cur = t & 1;
        if (t + 1 < ntiles) {
            const int k0 = (t + 1) << 4;
            const int nb = cur ^ 1;
            cp16(&As[nb][lar0][lac0], A + (size_t)(m0 + lar0) * K + k0 + lac0);
            cp16(&As[nb][lar1][lac1], A + (size_t)(m0 + lar1) * K + k0 + lac1);
            if (MAPB) {
                int col0 = n0 + lbn0, col1 = n0 + lbn1;
                cp16(&Bs[nb][lbk0][lbn0], Bm + ((size_t)(col0 >> 6) * K + k0 + lbk0) * HS_ + (col0 & 63));
                cp16(&Bs[nb][lbk1][lbn1], Bm + ((size_t)(col1 >> 6) * K + k0 + lbk1) * HS_ + (col1 & 63));
            } else {
                cp16(&Bs[nb][lbk0][lbn0], Bm + (size_t)(k0 + lbk0) * N + n0 + lbn0);
                cp16(&Bs[nb][lbk1][lbn1], Bm + (size_t)(k0 + lbk1) * N + n0 + lbn1);
            }
            cp_commit();
            cp_wait<1>();
        } else {
            cp_wait<0>();
        }
        __syncthreads();

        #pragma unroll
        for (int ks = 0; ks < 2; ++ks) {
            const int kb = ks * 8;
            float bf0[4], bf1[4];
            #pragma unroll
            for (int u = 0; u < 4; ++u) {
                bf0[u] = f2tf(Bs[cur][kb + tig    ][wn + u*8 + gid]);
                bf1[u] = f2tf(Bs[cur][kb + tig + 4][wn + u*8 + gid]);
            }
            #pragma unroll
            for (int tt = 0; tt < 4; ++tt) {
                const int rr = wm + tt * 16;
                float a0 = As[cur][rr + gid    ][kb + tig];
                float a1 = As[cur][rr + gid + 8][kb + tig];
                float a2 = As[cur][rr + gid    ][kb + tig + 4];
                float a3 = As[cur][rr + gid + 8][kb + tig + 4];
                #pragma unroll
                for (int u = 0; u < 4; ++u)
                    mma_tf32(acc[tt][u][0], acc[tt][u][1], acc[tt][u][2], acc[tt][u][3],
                             a0, a1, a2, a3, bf0[u], bf1[u]);
            }
        }
        __syncthreads();
    }

    // ---- epilogue ----
    #pragma unroll
    for (int t = 0; t < 4; ++t) {
        #pragma unroll
        for (int u = 0; u < 4; ++u) {
            const int m = m0 + wm + t*16 + gid;
            const int n = n0 + wn + u*8 + tig*2;
            float v0 = acc[t][u][0], v1 = acc[t][u][1];
            float v2 = acc[t][u][2], v3 = acc[t][u][3];
            if (HASBIAS) { float b0 = bias[n], b1 = bias[n+1]; v0 += b0; v1 += b1; v2 += b0; v3 += b1; }
            if (RELU) { v0 = fmaxf(v0, 0.f); v1 = fmaxf(v1, 0.f); v2 = fmaxf(v2, 0.f); v3 = fmaxf(v3, 0.f); }
            if (ROUND) { v0 = f2tf(v0); v1 = f2tf(v1); v2 = f2tf(v2); v3 = f2tf(v3); }
            if (ADDRES) {
                const float2 r0 = *(const float2*)(res + (size_t)m * N + n);
                const float2 r1 = *(const float2*)(res + (size_t)(m+8) * N + n);
                v0 += r0.x; v1 += r0.y; v2 += r1.x; v3 += r1.y;
            }
            *(float2*)(C + (size_t)m * N + n)       = make_float2(v0, v1);
            *(float2*)(C + (size_t)(m+8) * N + n)   = make_float2(v2, v3);
        }
    }
}

// ---------------- Flash attention (R7 exact): static smem, 128 thr, 64-row CTA ----------------
__global__ __launch_bounds__(128) void flash_kernel(const float* __restrict__ embds,
                                                    float* __restrict__ out)
{
    __shared__ float Qs[64][68];
    __shared__ float Ks[32][68];
    __shared__ float Vs[32][72];
    __shared__ float Ps[64][36];

    const int it = gridDim.x - 1 - blockIdx.x;   // heavy tiles first
    const int bh = blockIdx.y;
    const int b = bh >> 4, h = bh & 15;
    const int tid = threadIdx.x, warp = tid >> 5, lane = tid & 31;
    const int gid = lane >> 2, tig = lane & 3;
    const int i0 = it * 64;
    const int wr = i0 + warp * 16;

    #pragma unroll
    for (int l = 0; l < 8; ++l) {
        int idx = l * 128 + tid;
        int r = idx >> 4, e4 = (idx & 15) * 4;
        float4 qv = *(const float4*)(g_q + (((size_t)(b*T_ + i0 + r))*H_ + h)*HS_ + e4);
        qv.x = f2tf(qv.x); qv.y = f2tf(qv.y); qv.z = f2tf(qv.z); qv.w = f2tf(qv.w);
        *(float4*)(&Qs[r][e4]) = qv;
    }

    float oacc[8][4];
    #pragma unroll
    for (int u = 0; u < 8; ++u)
        #pragma unroll
        for (int c = 0; c < 4; ++c) oacc[u][c] = 0.f;
    float mrow[2] = {-1e30f, -1e30f};
    float lrow[2] = {0.f, 0.f};

    const int njc = 2*it + 2;
    for (int jc = 0; jc < njc; ++jc) {
        const int j0 = jc * 32;
        __syncthreads();
        #pragma unroll
        for (int l = 0; l < 4; ++l) {
            int idx = l * 128 + tid;
            int r = idx >> 4, e4 = (idx & 15) * 4;
            const size_t grow = (((size_t)(b*T_ + j0 + r))*H_ + h)*HS_ + e4;
            float4 kv = *(const float4*)(g_k + grow);
            kv.x = f2tf(kv.x); kv.y = f2tf(kv.y); kv.z = f2tf(kv.z); kv.w = f2tf(kv.w);
            *(float4*)(&Ks[r][e4]) = kv;
            float4 vv = *(const float4*)(g_v + grow);
            vv.x = f2tf(vv.x); vv.y = f2tf(vv.y); vv.z = f2tf(vv.z); vv.w = f2tf(vv.w);
            *(float4*)(&Vs[r][e4]) = vv;
        }
        __syncthreads();

        if (j0 <= wr + 15) {
            float sacc[4][4];
            #pragma unroll
            for (int u = 0; u < 4; ++u)
                #pragma unroll
                for (int c = 0; c < 4; ++c) sacc[u][c] = 0.f;
            #pragma unroll
            for (int kc = 0; kc < 8; ++kc) {
                const int kb = kc * 8;
                float a0 = Qs[warp*16 + gid    ][kb + tig];
                float a1 = Qs[warp*16 + gid + 8][kb + tig];
                float a2 = Qs[warp*16 + gid    ][kb + tig + 4];
                float a3 = Qs[warp*16 + gid + 8][kb + tig + 4];
                #pragma unroll
                for (int u = 0; u < 4; ++u) {
                    float b0 = Ks[u*8 + gid][kb + tig];
                    float b1 = Ks[u*8 + gid][kb + tig + 4];
                    mma_tf32(sacc[u][0], sacc[u][1], sacc[u][2], sacc[u][3],
                             a0, a1, a2, a3, b0, b1);
                }
            }

            const bool maskneed = (j0 + 31 > wr);
            #pragma unroll
            for (int rh = 0; rh < 2; ++rh) {
                const int row = wr + gid + rh*8;
                float tmax = -1e30f;
                #pragma unroll
                for (int u = 0; u < 4; ++u) {
                    float x0 = sacc[u][rh*2    ] * 0.03125f;
                    float x1 = sacc[u][rh*2 + 1] * 0.03125f;
                    if (maskneed) {
                        const int c = j0 + u*8 + tig*2;
                        if (c     > row) x0 = -1e30f;
                        if (c + 1 > row) x1 = -1e30f;
                    }
                    sacc[u][rh*2    ] = x0;
                    sacc[u][rh*2 + 1] = x1;
                    tmax = fmaxf(tmax, fmaxf(x0, x1));
                }
                tmax = fmaxf(tmax, __shfl_xor_sync(0xffffffffu, tmax, 1));
                tmax = fmaxf(tmax, __shfl_xor_sync(0xffffffffu, tmax, 2));
                const float mnew = fmaxf(mrow[rh], tmax);
                const float corr = __expf(mrow[rh] - mnew);
                float rsum = 0.f;
                #pragma unroll
                for (int u = 0; u < 4; ++u) {
                    float p0 = __expf(sacc[u][rh*2    ] - mnew);
                    float p1 = __expf(sacc[u][rh*2 + 1] - mnew);
                    rsum += p0 + p1;
                    *(float2*)(&Ps[warp*16 + gid + rh*8][u*8 + tig*2]) =
                        make_float2(f2tf(p0), f2tf(p1));
                }
                #pragma unroll
                for (int uu = 0; uu < 8; ++uu) {
                    oacc[uu][rh*2    ] *= corr;
                    oacc[uu][rh*2 + 1] *= corr;
                }
                rsum += __shfl_xor_sync(0xffffffffu, rsum, 1);
                rsum += __shfl_xor_sync(0xffffffffu, rsum, 2);
                lrow[rh] = lrow[rh] * corr + rsum;
                mrow[rh] = mnew;
            }
            __syncwarp();

            #pragma unroll
            for (int kc = 0; kc < 4; ++kc) {
                const int kb = kc * 8;
                float a0 = Ps[warp*16 + gid    ][kb + tig];
                float a1 = Ps[warp*16 + gid + 8][kb + tig];
                float a2 = Ps[warp*16 + gid    ][kb + tig + 4];
                float a3 = Ps[warp*16 + gid + 8][kb + tig + 4];
                #pragma unroll
                for (int u = 0; u < 8; ++u) {
                    float b0 = Vs[kb + tig    ][u*8 + gid];
                    float b1 = Vs[kb + tig + 4][u*8 + gid];
                    mma_tf32(oacc[u][0], oacc[u][1], oacc[u][2], oacc[u][3],
                             a0, a1, a2, a3, b0, b1);
                }
            }
        }
    }

    #pragma unroll
    for (int rh = 0; rh < 2; ++rh) {
        const int t = wr + gid + rh*8;
        const float inv = 1.0f / lrow[rh];
        #pragma unroll
        for (int u = 0; u < 8; ++u) {
            const int d = h * HS_ + u*8 + tig*2;
            const size_t o = ((size_t)(b*T_ + t))*D_ + d;
            const float2 e = *(const float2*)(embds + o);
            *(float2*)(out + o) = make_float2(e.x + oacc[u][rh*2    ]*inv,
                                              e.y + oacc[u][rh*2 + 1]*inv);
        }
    }
}

// ---------------- Launcher ----------------
extern "C" void kernel_launch(void* const* d_in, const int* in_sizes, int n_in,
                              void* d_out, int out_size)
{
    const float* embds = (const float*)d_in[0];
    const float* Wq    = (const float*)d_in[1];
    const float* Wk    = (const float*)d_in[2];
    const float* Wv    = (const float*)d_in[3];
    const float* ln1g  = (const float*)d_in[4];
    const float* ln1b  = (const float*)d_in[5];
    const float* ln2g  = (const float*)d_in[6];
    const float* ln2b  = (const float*)d_in[7];
    const float* W1    = (const float*)d_in[8];
    const float* b1    = (const float*)d_in[9];
    const float* W2    = (const float*)d_in[10];
    const float* b2    = (const float*)d_in[11];
    float* out = (float*)d_out;

    float *xln, *q, *k, *v, *res1, *ffh;
    cudaGetSymbolAddress((void**)&xln,  g_xln);
    cudaGetSymbolAddress((void**)&q,    g_q);
    cudaGetSymbolAddress((void**)&k,    g_k);
    cudaGetSymbolAddress((void**)&v,    g_v);
    cudaGetSymbolAddress((void**)&res1, g_res1);
    cudaGetSymbolAddress((void**)&ffh,  g_ffh);

    // 1. LN1 (tf32-rounded out)
    ln_kernel<<<BT_, 256>>>(embds, ln1g, ln1b, xln);

    // 2. Q, K, V projections -> [B,T,H,HS] (rounded outputs feed flash)
    {
        dim3 grid(D_ / 128, BT_ / 128);   // (8, 32)
        tgemm_kernel<true,  false, false, false, true><<<grid, 256>>>(xln, Wq, nullptr, nullptr, q, BT_, D_, D_);
        tgemm_kernel<true,  false, false, false, true><<<grid, 256>>>(xln, Wk, nullptr, nullptr, k, BT_, D_, D_);
        tgemm_kernel<true,  false, false, false, true><<<grid, 256>>>(xln, Wv, nullptr, nullptr, v, BT_, D_, D_);
    }

    // 3. Flash attention + head-concat + residual -> res1
    flash_kernel<<<dim3(T_/64, BH_), 128>>>(embds, res1);

    // 4. LN2 (tf32-rounded out)
    ln_kernel<<<BT_, 256>>>(res1, ln2g, ln2b, xln);

    // 5. FFN1: relu(y @ W1 + b1) (rounded) -> ffh
    tgemm_kernel<false, true, true,  false, true><<<dim3(4*D_ / 128, BT_ / 128), 256>>>(xln, W1, b1, nullptr, ffh, BT_, 4*D_, D_);

    // 6. FFN2: ffh @ W2 + b2 + res1 -> out (exact epilogue)
    tgemm_kernel<false, true, false, true,  false><<<dim3(D_ / 128, BT_ / 128), 256>>>(ffh, W2, b2, res1, out, BT_, D_, 4*D_);
}